// round 10
// baseline (speedup 1.0000x reference)
#include <cuda_runtime.h>
#include <cstdint>

#define N_TX   500000
#define N_ACC  100000
#define NE     1000000

#define SCAN_BS   1024
#define N_SCAN_BLKS ((N_TX + SCAN_BS - 1) / SCAN_BS)   // 489

// CSR scratch
__device__ int  g_deg[N_TX];
__device__ int  g_off[N_TX];     // absolute offsets; bumped to END by place
__device__ int2 g_sedge[NE];     // (src, dst) sorted by dst
__device__ int  g_alloc_ctr;

// ---------------------------------------------------------------------------
__global__ void zero_kernel() {
    int i = blockIdx.x * blockDim.x + threadIdx.x;
    if (i < N_TX) g_deg[i] = 0;
    if (i == 0) g_alloc_ctr = 0;
}

__global__ void hist_kernel(const int* __restrict__ dst_idx) {
    int e = blockIdx.x * blockDim.x + threadIdx.x;
    if (e < NE) atomicAdd(&g_deg[dst_idx[e]], 1);
}

// Block-scan + one global atomic per 1024-row block -> absolute g_off.
// (128-row compute tiles sit inside one 1024-row alloc block, so each compute
// tile's edges stay contiguous.)
__global__ void alloc_kernel() {
    __shared__ int sh[SCAN_BS];
    __shared__ int base_s;
    int t = threadIdx.x;
    int idx = blockIdx.x * SCAN_BS + t;
    int v = (idx < N_TX) ? g_deg[idx] : 0;
    sh[t] = v;
    __syncthreads();
    #pragma unroll
    for (int o = 1; o < SCAN_BS; o <<= 1) {
        int add = (t >= o) ? sh[t - o] : 0;
        __syncthreads();
        sh[t] += add;
        __syncthreads();
    }
    if (t == SCAN_BS - 1) base_s = atomicAdd(&g_alloc_ctr, sh[t]);
    __syncthreads();
    if (idx < N_TX) g_off[idx] = base_s + sh[t] - v;   // exclusive start
}

__global__ void place_kernel(const int* __restrict__ src_idx,
                             const int* __restrict__ dst_idx) {
    int e = blockIdx.x * blockDim.x + threadIdx.x;
    if (e >= NE) return;
    int d = dst_idx[e];
    int pos = atomicAdd(&g_off[d], 1);
    g_sedge[pos] = make_int2(src_idx[e], d);
}

// ---------------------------------------------------------------------------
// Fused compute kernel: edge-parallel gather (smem f32 atomics) + bf16 hi/lo
// 3-product m16n8k16 GEMM + relu + logit head. 128 threads / 128 rows.
// ---------------------------------------------------------------------------
#define RBLK   128
#define A_STR  52    // u32/row; 52%32==20 -> frag bank=(20g+t): bijective
#define B_STR  72    // u32; 72%32==8 -> frag bank = 8t+g, bijective
#define H_STR  68    // restage stride (floats)
#define AGG_S  33    // agg row stride (floats); 33%32==1 -> spread banks

// dynamic smem (u32 units): Ahi | Alo | Bh | Bl | agg
#define SM_AHI 0
#define SM_ALO (RBLK * A_STR)                 // 6656
#define SM_BH  (SM_ALO + RBLK * A_STR)        // 13312
#define SM_BL  (SM_BH + 48 * B_STR)           // 16768
#define SM_AGG (SM_BL + 48 * B_STR)           // 20224
#define SM_TOT (SM_AGG + RBLK * AGG_S)        // 24448 u32
#define SMEM_BYTES (SM_TOT * 4)               // 97792 B

// pack two f32 into bf16x2 hi + residual lo (v0 -> low half = even k)
__device__ __forceinline__ void pack_pair(float v0, float v1,
                                          uint32_t& hi, uint32_t& lo) {
    uint32_t h;
    asm("cvt.rn.bf16x2.f32 %0, %1, %2;" : "=r"(h) : "f"(v1), "f"(v0));
    float f0 = __uint_as_float(h << 16);
    float f1 = __uint_as_float(h & 0xffff0000u);
    float r0 = v0 - f0, r1 = v1 - f1;
    uint32_t l;
    asm("cvt.rn.bf16x2.f32 %0, %1, %2;" : "=r"(l) : "f"(r1), "f"(r0));
    hi = h; lo = l;
}

__device__ __forceinline__ void mma16(float* c, const uint32_t* a, const uint32_t* b) {
    asm volatile(
        "mma.sync.aligned.m16n8k16.row.col.f32.bf16.bf16.f32 "
        "{%0,%1,%2,%3}, {%4,%5,%6,%7}, {%8,%9}, {%0,%1,%2,%3};"
        : "+f"(c[0]), "+f"(c[1]), "+f"(c[2]), "+f"(c[3])
        : "r"(a[0]), "r"(a[1]), "r"(a[2]), "r"(a[3]), "r"(b[0]), "r"(b[1]));
}

__global__ void __launch_bounds__(128, 2)
compute_kernel(const float* __restrict__ x_tx,
               const float* __restrict__ x_acc,
               const float* __restrict__ Wl,   // [32,64]
               const float* __restrict__ bl,   // [64]
               const float* __restrict__ Wr,   // [64,64]
               const float* __restrict__ Wout, // [64]
               const float* __restrict__ bout, // [1]
               float* __restrict__ out) {
    extern __shared__ uint32_t smem_u32[];
    uint32_t* Ahi = smem_u32 + SM_AHI;
    uint32_t* Alo = smem_u32 + SM_ALO;
    uint32_t* Bh  = smem_u32 + SM_BH;
    uint32_t* Blo = smem_u32 + SM_BL;
    float*    aggS = (float*)(smem_u32 + SM_AGG);
    float* restage = (float*)smem_u32;   // reused after GEMM
    __shared__ float bl_s[64];
    __shared__ float wout_s[64];

    const int tid  = threadIdx.x;
    const int wid  = tid >> 5;
    const int lane = tid & 31;
    const int r0   = blockIdx.x * RBLK;

    if (tid < 64) { bl_s[tid] = bl[tid]; wout_s[tid] = Wout[tid]; }

    // ---- Zero agg scratch ----
    #pragma unroll
    for (int i = tid; i < RBLK * AGG_S; i += 128) aggS[i] = 0.f;

    // ---- Stage x_tx row (thread = row) -> A kp 0..31 ----
    {
        const int r = r0 + tid;
        uint32_t* AhiR = Ahi + tid * A_STR;
        uint32_t* AloR = Alo + tid * A_STR;
        if (r < N_TX) {
            const float4* xr = (const float4*)(x_tx + (size_t)r * 64);
            #pragma unroll
            for (int j = 0; j < 16; j++) {
                float4 v = __ldcs(xr + j);   // streaming: read-once
                uint32_t h0, l0, h1, l1;
                pack_pair(v.x, v.y, h0, l0);
                pack_pair(v.z, v.w, h1, l1);
                AhiR[j * 2] = h0; AhiR[j * 2 + 1] = h1;
                AloR[j * 2] = l0; AloR[j * 2 + 1] = l1;
            }
        } else {
            #pragma unroll
            for (int j = 0; j < 32; j++) { AhiR[j] = 0u; AloR[j] = 0u; }
        }
    }

    // ---- Stage B = W^T [96 k][64 n] as bf16x2 k-pairs, hi/lo ----
    {
        const int n   = tid & 63;
        const int kp0 = (tid >> 6) * 24;
        for (int kp = kp0; kp < kp0 + 24; kp++) {
            int k0 = kp * 2;
            float w0 = (k0 < 64) ? Wr[k0 * 64 + n] : Wl[(k0 - 64) * 64 + n];
            int k1 = k0 + 1;
            float w1 = (k1 < 64) ? Wr[k1 * 64 + n] : Wl[(k1 - 64) * 64 + n];
            uint32_t h, l;
            pack_pair(w0, w1, h, l);
            Bh[kp * B_STR + n]  = h;
            Blo[kp * B_STR + n] = l;
        }
    }
    __syncthreads();

    // ---- Edge-parallel gather: block's edges are contiguous (sorted by dst).
    //      Threads stride over edges -> balanced regardless of degree skew. ----
    {
        const int r_last = (r0 + RBLK - 1 < N_TX) ? (r0 + RBLK - 1) : (N_TX - 1);
        const int e_end   = g_off[r_last];              // END ptr of last row
        const int e_start = g_off[r0] - g_deg[r0];      // START of first row
        const int ecnt    = e_end - e_start;
        for (int i = tid; i < ecnt; i += 128) {
            int2 ed = __ldcs(&g_sedge[e_start + i]);    // (src, dst), read-once
            const float4* p = (const float4*)(x_acc + (size_t)ed.x * 32);
            float* arow = aggS + (ed.y - r0) * AGG_S;
            #pragma unroll
            for (int j = 0; j < 8; j++) {
                float4 v = p[j];
                atomicAdd(arow + j * 4 + 0, v.x);
                atomicAdd(arow + j * 4 + 1, v.y);
                atomicAdd(arow + j * 4 + 2, v.z);
                atomicAdd(arow + j * 4 + 3, v.w);
            }
        }
    }
    __syncthreads();

    // ---- Mean + pack agg (thread = row) -> A kp 32..47 ----
    {
        const int r = r0 + tid;
        uint32_t* AhiR = Ahi + tid * A_STR;
        uint32_t* AloR = Alo + tid * A_STR;
        int cnt = (r < N_TX) ? g_deg[r] : 0;
        float inv = 1.f / (float)max(cnt, 1);
        const float* arow = aggS + tid * AGG_S;
        #pragma unroll
        for (int j = 0; j < 16; j++) {
            uint32_t h, l;
            pack_pair(arow[j * 2] * inv, arow[j * 2 + 1] * inv, h, l);
            AhiR[32 + j] = h;
            AloR[32 + j] = l;
        }
    }
    __syncthreads();

    const int t  = lane & 3;
    const int g  = lane >> 2;
    const int rb = wid * 32;

    // Accumulators [mtile][ntile][4], seeded with bias
    float acc[2][8][4];
    #pragma unroll
    for (int nt = 0; nt < 8; nt++) {
        float b0 = bl_s[nt * 8 + t * 2];
        float b1 = bl_s[nt * 8 + t * 2 + 1];
        #pragma unroll
        for (int mt = 0; mt < 2; mt++) {
            acc[mt][nt][0] = b0; acc[mt][nt][1] = b1;
            acc[mt][nt][2] = b0; acc[mt][nt][3] = b1;
        }
    }

    #pragma unroll
    for (int kt = 0; kt < 6; kt++) {
        const int kp0 = kt * 8;
        uint32_t ahi[2][4], alo[2][4];
        #pragma unroll
        for (int mt = 0; mt < 2; mt++) {
            const uint32_t* Ah = Ahi + (rb + mt * 16 + g) * A_STR + kp0 + t;
            const uint32_t* Al = Alo + (rb + mt * 16 + g) * A_STR + kp0 + t;
            ahi[mt][0] = Ah[0];
            ahi[mt][1] = Ah[8 * A_STR];
            ahi[mt][2] = Ah[4];
            ahi[mt][3] = Ah[8 * A_STR + 4];
            alo[mt][0] = Al[0];
            alo[mt][1] = Al[8 * A_STR];
            alo[mt][2] = Al[4];
            alo[mt][3] = Al[8 * A_STR + 4];
        }
        #pragma unroll
        for (int nt = 0; nt < 8; nt++) {
            const int n = nt * 8 + g;
            const uint32_t* Bp = Bh  + (kp0 + t) * B_STR + n;
            const uint32_t* Lp = Blo + (kp0 + t) * B_STR + n;
            uint32_t bh[2], blv[2];
            bh[0]  = Bp[0];
            bh[1]  = Bp[4 * B_STR];
            blv[0] = Lp[0];
            blv[1] = Lp[4 * B_STR];
            mma16(acc[0][nt], ahi[0], bh);
            mma16(acc[0][nt], alo[0], bh);
            mma16(acc[0][nt], ahi[0], blv);
            mma16(acc[1][nt], ahi[1], bh);
            mma16(acc[1][nt], alo[1], bh);
            mma16(acc[1][nt], ahi[1], blv);
        }
    }
    __syncthreads();   // done reading A/B; reuse smem as restage buffer

    // ---- Epilogue: relu + logit dot + restage ----
    #pragma unroll
    for (int mt = 0; mt < 2; mt++) {
        #pragma unroll
        for (int half = 0; half < 2; half++) {
            const int row = rb + mt * 16 + half * 8 + g;
            float* hrow = restage + row * H_STR;
            float partial = 0.f;
            #pragma unroll
            for (int nt = 0; nt < 8; nt++) {
                float h0 = fmaxf(acc[mt][nt][half * 2 + 0], 0.f);
                float h1 = fmaxf(acc[mt][nt][half * 2 + 1], 0.f);
                int col = nt * 8 + t * 2;
                partial += h0 * wout_s[col] + h1 * wout_s[col + 1];
                *(float2*)(hrow + col) = make_float2(h0, h1);
            }
            partial += __shfl_xor_sync(0xffffffffu, partial, 1);
            partial += __shfl_xor_sync(0xffffffffu, partial, 2);
            int r = r0 + row;
            if (t == 0 && r < N_TX) __stcs(out + r, partial + bout[0]);
        }
    }
    __syncthreads();

    // ---- Coalesced tx_x store (streaming) ----
    {
        const int vr = (N_TX - r0 < RBLK) ? (N_TX - r0) : RBLK;
        float4* dst = (float4*)(out + N_TX + (size_t)r0 * 64);
        #pragma unroll
        for (int i = tid; i < RBLK * 16; i += 128) {
            int row = i >> 4, c = i & 15;
            if (row < vr)
                __stcs(dst + row * 16 + c,
                       *(float4*)(restage + row * H_STR + c * 4));
        }
    }
}

// ---------------------------------------------------------------------------
extern "C" void kernel_launch(void* const* d_in, const int* in_sizes, int n_in,
                              void* d_out, int out_size) {
    const float* x_tx     = (const float*)d_in[0];
    const float* x_acc    = (const float*)d_in[1];
    const int*   pays_src = (const int*)d_in[2];
    const int*   pays_dst = (const int*)d_in[3];
    // d_in[4], d_in[5]: rev edges — dead code in reference (h_acc unused)
    const float* Wl_pays  = (const float*)d_in[6];
    const float* bl_pays  = (const float*)d_in[7];
    const float* Wr_pays  = (const float*)d_in[8];
    // d_in[9..11]: rev weights — unused
    const float* W_out    = (const float*)d_in[12];
    const float* b_out    = (const float*)d_in[13];
    float* out = (float*)d_out;   // [logits(500000) | tx_x(500000*64)]

    cudaFuncSetAttribute(compute_kernel,
                         cudaFuncAttributeMaxDynamicSharedMemorySize, SMEM_BYTES);

    zero_kernel<<<(N_TX + 255) / 256, 256>>>();
    hist_kernel<<<(NE + 255) / 256, 256>>>(pays_dst);
    alloc_kernel<<<N_SCAN_BLKS, SCAN_BS>>>();
    place_kernel<<<(NE + 255) / 256, 256>>>(pays_src, pays_dst);
    compute_kernel<<<(N_TX + RBLK - 1) / RBLK, RBLK, SMEM_BYTES>>>(
        x_tx, x_acc, Wl_pays, bl_pays, Wr_pays, W_out, b_out, out);
}

// round 11
// speedup vs baseline: 2.8486x; 2.8486x over previous
#include <cuda_runtime.h>
#include <cuda_fp16.h>
#include <cstdint>

#define N_TX   500000
#define N_ACC  100000
#define NE     1000000

#define SCAN_BS   1024
#define N_SCAN_BLKS ((N_TX + SCAN_BS - 1) / SCAN_BS)   // 489

// CSR scratch
__device__ int g_deg[N_TX];
__device__ int g_off[N_TX];      // absolute offsets; bumped to END by place
__device__ int g_sorted_src[NE];
__device__ int g_alloc_ctr;

// ---------------------------------------------------------------------------
__global__ void zero_kernel() {
    int i = blockIdx.x * blockDim.x + threadIdx.x;
    if (i < N_TX) g_deg[i] = 0;
    if (i == 0) g_alloc_ctr = 0;
}

__global__ void hist_kernel(const int* __restrict__ dst_idx) {
    int e = blockIdx.x * blockDim.x + threadIdx.x;
    if (e < NE) atomicAdd(&g_deg[dst_idx[e]], 1);
}

// Fused scan: block-scan + one global atomic per 1024-row block -> absolute g_off
__global__ void alloc_kernel() {
    __shared__ int sh[SCAN_BS];
    __shared__ int base_s;
    int t = threadIdx.x;
    int idx = blockIdx.x * SCAN_BS + t;
    int v = (idx < N_TX) ? g_deg[idx] : 0;
    sh[t] = v;
    __syncthreads();
    #pragma unroll
    for (int o = 1; o < SCAN_BS; o <<= 1) {
        int add = (t >= o) ? sh[t - o] : 0;
        __syncthreads();
        sh[t] += add;
        __syncthreads();
    }
    if (t == SCAN_BS - 1) base_s = atomicAdd(&g_alloc_ctr, sh[t]);
    __syncthreads();
    if (idx < N_TX) g_off[idx] = base_s + sh[t] - v;   // exclusive start
}

__global__ void place_kernel(const int* __restrict__ src_idx,
                             const int* __restrict__ dst_idx) {
    int e = blockIdx.x * blockDim.x + threadIdx.x;
    if (e >= NE) return;
    int pos = atomicAdd(&g_off[dst_idx[e]], 1);
    g_sorted_src[pos] = src_idx[e];
}

// ---------------------------------------------------------------------------
// Fused compute kernel (R9 structure, fp16): CSR gather-mean +
// [x|agg][128x96] @ W^T[96x64] via mma.sync m16n8k16 f16.
// A plain fp16 (uncorrected, 2^-12); B split hi/lo -> 2 products.
// 128 threads, 4 warps, warp = 32 rows (2 m16 tiles). 54 KB smem -> 4 CTA/SM.
// ---------------------------------------------------------------------------
#define RBLK   128
#define A_STR  52    // u32/row (need >=48). 52%32==20 -> frag bank=(20g+t): bijective
#define B_STR  72    // u32; 72%32==8 -> frag bank = 8t+g, bijective
#define H_STR  68    // restage stride (floats)

// dynamic smem (u32 units): Ah | Bh | Bl
#define SM_AH  0
#define SM_BH  (RBLK * A_STR)                 // 6656
#define SM_BL  (SM_BH + 48 * B_STR)           // 10112
#define SM_TOT (SM_BL + 48 * B_STR)           // 13568 u32
#define SMEM_BYTES (SM_TOT * 4)               // 54272 B

// pack two f32 -> f16x2 (v0 -> low half = even k)
__device__ __forceinline__ uint32_t pack_h2(float v0, float v1) {
    __half2 h = __floats2half2_rn(v0, v1);
    return *(uint32_t*)&h;
}

// pack with residual: hi = f16x2(v), lo = f16x2(v - f32(hi))
__device__ __forceinline__ void pack_h2_split(float v0, float v1,
                                              uint32_t& hi, uint32_t& lo) {
    __half2 h = __floats2half2_rn(v0, v1);
    float2 b = __half22float2(h);
    __half2 l = __floats2half2_rn(v0 - b.x, v1 - b.y);
    hi = *(uint32_t*)&h;
    lo = *(uint32_t*)&l;
}

__device__ __forceinline__ void mma16(float* c, const uint32_t* a, const uint32_t* b) {
    asm volatile(
        "mma.sync.aligned.m16n8k16.row.col.f32.f16.f16.f32 "
        "{%0,%1,%2,%3}, {%4,%5,%6,%7}, {%8,%9}, {%0,%1,%2,%3};"
        : "+f"(c[0]), "+f"(c[1]), "+f"(c[2]), "+f"(c[3])
        : "r"(a[0]), "r"(a[1]), "r"(a[2]), "r"(a[3]), "r"(b[0]), "r"(b[1]));
}

__global__ void __launch_bounds__(128, 4)
compute_kernel(const float* __restrict__ x_tx,
               const float* __restrict__ x_acc,
               const float* __restrict__ Wl,   // [32,64]
               const float* __restrict__ bl,   // [64]
               const float* __restrict__ Wr,   // [64,64]
               const float* __restrict__ Wout, // [64]
               const float* __restrict__ bout, // [1]
               float* __restrict__ out) {
    extern __shared__ uint32_t smem_u32[];
    uint32_t* Ah = smem_u32 + SM_AH;
    uint32_t* Bh = smem_u32 + SM_BH;
    uint32_t* Bl = smem_u32 + SM_BL;
    float* restage = (float*)smem_u32;   // overlays everything after GEMM
    __shared__ float bl_s[64];
    __shared__ float wout_s[64];

    const int tid  = threadIdx.x;
    const int wid  = tid >> 5;
    const int lane = tid & 31;
    const int r0   = blockIdx.x * RBLK;

    if (tid < 64) { bl_s[tid] = bl[tid]; wout_s[tid] = Wout[tid]; }

    // ---- Stage A row (thread = row): x_tx -> kp 0..31, agg -> kp 32..47 ----
    {
        const int r = r0 + tid;
        uint32_t* AR = Ah + tid * A_STR;

        if (r < N_TX) {
            const float4* xr = (const float4*)(x_tx + (size_t)r * 64);
            #pragma unroll
            for (int j = 0; j < 16; j++) {
                float4 v = __ldcs(xr + j);   // streaming: read-once
                AR[j * 2]     = pack_h2(v.x, v.y);
                AR[j * 2 + 1] = pack_h2(v.z, v.w);
            }
        } else {
            #pragma unroll
            for (int j = 0; j < 32; j++) AR[j] = 0u;
        }

        // CSR gather-mean (x_acc default policy -> L2-resident)
        float a[32];
        #pragma unroll
        for (int d = 0; d < 32; d++) a[d] = 0.f;
        int cnt = 0;
        if (r < N_TX) {
            cnt = g_deg[r];
            int end = g_off[r];           // END pointer after place
            int start = end - cnt;
            for (int i = 0; i < cnt; i++) {
                int s = __ldcs(g_sorted_src + start + i);
                const float4* p = (const float4*)(x_acc + (size_t)s * 32);
                #pragma unroll
                for (int j = 0; j < 8; j++) {
                    float4 v = p[j];
                    a[j * 4 + 0] += v.x; a[j * 4 + 1] += v.y;
                    a[j * 4 + 2] += v.z; a[j * 4 + 3] += v.w;
                }
            }
        }
        float inv = 1.f / (float)max(cnt, 1);
        #pragma unroll
        for (int j = 0; j < 16; j++)
            AR[32 + j] = pack_h2(a[j * 2] * inv, a[j * 2 + 1] * inv);
    }

    // ---- Stage B = W^T [96 k][64 n] as f16x2 k-pairs, hi/lo ----
    {
        const int n   = tid & 63;
        const int kp0 = (tid >> 6) * 24;
        for (int kp = kp0; kp < kp0 + 24; kp++) {
            int k0 = kp * 2;
            float w0 = (k0 < 64) ? Wr[k0 * 64 + n] : Wl[(k0 - 64) * 64 + n];
            int k1 = k0 + 1;
            float w1 = (k1 < 64) ? Wr[k1 * 64 + n] : Wl[(k1 - 64) * 64 + n];
            uint32_t h, l;
            pack_h2_split(w0, w1, h, l);
            Bh[kp * B_STR + n] = h;
            Bl[kp * B_STR + n] = l;
        }
    }
    __syncthreads();

    const int t  = lane & 3;
    const int g  = lane >> 2;
    const int rb = wid * 32;

    // Accumulators [mtile][ntile][4], seeded with bias
    float acc[2][8][4];
    #pragma unroll
    for (int nt = 0; nt < 8; nt++) {
        float b0 = bl_s[nt * 8 + t * 2];
        float b1 = bl_s[nt * 8 + t * 2 + 1];
        #pragma unroll
        for (int mt = 0; mt < 2; mt++) {
            acc[mt][nt][0] = b0; acc[mt][nt][1] = b1;
            acc[mt][nt][2] = b0; acc[mt][nt][3] = b1;
        }
    }

    #pragma unroll
    for (int kt = 0; kt < 6; kt++) {
        const int kp0 = kt * 8;
        uint32_t af[2][4];
        #pragma unroll
        for (int mt = 0; mt < 2; mt++) {
            const uint32_t* Ap = Ah + (rb + mt * 16 + g) * A_STR + kp0 + t;
            af[mt][0] = Ap[0];                 // (row g,   kp t)
            af[mt][1] = Ap[8 * A_STR];         // (row g+8, kp t)
            af[mt][2] = Ap[4];                 // (row g,   kp t+4)
            af[mt][3] = Ap[8 * A_STR + 4];     // (row g+8, kp t+4)
        }
        #pragma unroll
        for (int nt = 0; nt < 8; nt++) {
            const int n = nt * 8 + g;
            const uint32_t* Bp = Bh + (kp0 + t) * B_STR + n;
            const uint32_t* Lp = Bl + (kp0 + t) * B_STR + n;
            uint32_t bh[2], blv[2];
            bh[0]  = Bp[0];
            bh[1]  = Bp[4 * B_STR];
            blv[0] = Lp[0];
            blv[1] = Lp[4 * B_STR];
            mma16(acc[0][nt], af[0], bh);
            mma16(acc[0][nt], af[0], blv);
            mma16(acc[1][nt], af[1], bh);
            mma16(acc[1][nt], af[1], blv);
        }
    }
    __syncthreads();   // done reading A/B; reuse smem as restage buffer

    // ---- Epilogue: relu + logit dot + restage ----
    #pragma unroll
    for (int mt = 0; mt < 2; mt++) {
        #pragma unroll
        for (int half = 0; half < 2; half++) {
            const int row = rb + mt * 16 + half * 8 + g;
            float* hrow = restage + row * H_STR;
            float partial = 0.f;
            #pragma unroll
            for (int nt = 0; nt < 8; nt++) {
                float h0 = fmaxf(acc[mt][nt][half * 2 + 0], 0.f);
                float h1 = fmaxf(acc[mt][nt][half * 2 + 1], 0.f);
                int col = nt * 8 + t * 2;
                partial += h0 * wout_s[col] + h1 * wout_s[col + 1];
                *(float2*)(hrow + col) = make_float2(h0, h1);
            }
            partial += __shfl_xor_sync(0xffffffffu, partial, 1);
            partial += __shfl_xor_sync(0xffffffffu, partial, 2);
            int r = r0 + row;
            if (t == 0 && r < N_TX) __stcs(out + r, partial + bout[0]);
        }
    }
    __syncthreads();

    // ---- Coalesced tx_x store (streaming) ----
    {
        const int vr = (N_TX - r0 < RBLK) ? (N_TX - r0) : RBLK;
        float4* dst = (float4*)(out + N_TX + (size_t)r0 * 64);
        #pragma unroll
        for (int i = tid; i < RBLK * 16; i += 128) {
            int row = i >> 4, c = i & 15;
            if (row < vr)
                __stcs(dst + row * 16 + c,
                       *(float4*)(restage + row * H_STR + c * 4));
        }
    }
}

// ---------------------------------------------------------------------------
extern "C" void kernel_launch(void* const* d_in, const int* in_sizes, int n_in,
                              void* d_out, int out_size) {
    const float* x_tx     = (const float*)d_in[0];
    const float* x_acc    = (const float*)d_in[1];
    const int*   pays_src = (const int*)d_in[2];
    const int*   pays_dst = (const int*)d_in[3];
    // d_in[4], d_in[5]: rev edges — dead code in reference (h_acc unused)
    const float* Wl_pays  = (const float*)d_in[6];
    const float* bl_pays  = (const float*)d_in[7];
    const float* Wr_pays  = (const float*)d_in[8];
    // d_in[9..11]: rev weights — unused
    const float* W_out    = (const float*)d_in[12];
    const float* b_out    = (const float*)d_in[13];
    float* out = (float*)d_out;   // [logits(500000) | tx_x(500000*64)]

    cudaFuncSetAttribute(compute_kernel,
                         cudaFuncAttributeMaxDynamicSharedMemorySize, SMEM_BYTES);

    zero_kernel<<<(N_TX + 255) / 256, 256>>>();
    hist_kernel<<<(NE + 255) / 256, 256>>>(pays_dst);
    alloc_kernel<<<N_SCAN_BLKS, SCAN_BS>>>();
    place_kernel<<<(NE + 255) / 256, 256>>>(pays_src, pays_dst);
    compute_kernel<<<(N_TX + RBLK - 1) / RBLK, RBLK, SMEM_BYTES>>>(
        x_tx, x_acc, Wl_pays, bl_pays, Wr_pays, W_out, b_out, out);
}

// round 12
// speedup vs baseline: 3.0339x; 1.0651x over previous
#include <cuda_runtime.h>
#include <cuda_fp16.h>
#include <cstdint>

#define N_TX   500000
#define N_ACC  100000
#define NE     1000000

#define SCAN_BS   1024
#define N_SCAN_BLKS ((N_TX + SCAN_BS - 1) / SCAN_BS)   // 489

// CSR scratch
__device__ int g_deg[N_TX];
__device__ int g_off[N_TX];      // absolute offsets; bumped to END by place
__device__ int g_sorted_src[NE];
__device__ int g_alloc_ctr;

// ---------------------------------------------------------------------------
__global__ void zero_kernel() {
    int i = blockIdx.x * blockDim.x + threadIdx.x;
    if (i < N_TX) g_deg[i] = 0;
    if (i == 0) g_alloc_ctr = 0;
}

__global__ void hist_kernel(const int* __restrict__ dst_idx) {
    int e = blockIdx.x * blockDim.x + threadIdx.x;
    if (e < NE) atomicAdd(&g_deg[dst_idx[e]], 1);
}

// Fused scan: block-scan + one global atomic per 1024-row block -> absolute g_off
__global__ void alloc_kernel() {
    __shared__ int sh[SCAN_BS];
    __shared__ int base_s;
    int t = threadIdx.x;
    int idx = blockIdx.x * SCAN_BS + t;
    int v = (idx < N_TX) ? g_deg[idx] : 0;
    sh[t] = v;
    __syncthreads();
    #pragma unroll
    for (int o = 1; o < SCAN_BS; o <<= 1) {
        int add = (t >= o) ? sh[t - o] : 0;
        __syncthreads();
        sh[t] += add;
        __syncthreads();
    }
    if (t == SCAN_BS - 1) base_s = atomicAdd(&g_alloc_ctr, sh[t]);
    __syncthreads();
    if (idx < N_TX) g_off[idx] = base_s + sh[t] - v;   // exclusive start
}

__global__ void place_kernel(const int* __restrict__ src_idx,
                             const int* __restrict__ dst_idx) {
    int e = blockIdx.x * blockDim.x + threadIdx.x;
    if (e >= NE) return;
    int pos = atomicAdd(&g_off[dst_idx[e]], 1);
    g_sorted_src[pos] = src_idx[e];
}

// ---------------------------------------------------------------------------
// Fused compute kernel: CSR gather-mean + [x|agg][128x96] @ W^T[96x64] via
// mma.sync m16n8k16 f16, SINGLE product (A and B plain fp16, err ~3.5e-4).
// 128 threads, 4 warps, warp = 32 rows (2 m16 tiles). 40 KB smem -> 5 CTA/SM.
// ---------------------------------------------------------------------------
#define RBLK   128
#define A_STR  52    // u32/row (need >=48). 52%32==20 -> frag bank=(20g+t): bijective
#define B_STR  72    // u32; 72%32==8 -> frag bank = 8t+g, bijective
#define H_STR  68    // restage stride (floats)

// dynamic smem (u32 units): Ah | Bh
#define SM_AH  0
#define SM_BH  (RBLK * A_STR)                 // 6656
#define SM_TOT (SM_BH + 48 * B_STR)           // 10112 u32
#define SMEM_BYTES (SM_TOT * 4)               // 40448 B

// pack two f32 -> f16x2 (v0 -> low half = even k)
__device__ __forceinline__ uint32_t pack_h2(float v0, float v1) {
    __half2 h = __floats2half2_rn(v0, v1);
    return *(uint32_t*)&h;
}

__device__ __forceinline__ void mma16(float* c, const uint32_t* a, const uint32_t* b) {
    asm volatile(
        "mma.sync.aligned.m16n8k16.row.col.f32.f16.f16.f32 "
        "{%0,%1,%2,%3}, {%4,%5,%6,%7}, {%8,%9}, {%0,%1,%2,%3};"
        : "+f"(c[0]), "+f"(c[1]), "+f"(c[2]), "+f"(c[3])
        : "r"(a[0]), "r"(a[1]), "r"(a[2]), "r"(a[3]), "r"(b[0]), "r"(b[1]));
}

__global__ void __launch_bounds__(128, 5)
compute_kernel(const float* __restrict__ x_tx,
               const float* __restrict__ x_acc,
               const float* __restrict__ Wl,   // [32,64]
               const float* __restrict__ bl,   // [64]
               const float* __restrict__ Wr,   // [64,64]
               const float* __restrict__ Wout, // [64]
               const float* __restrict__ bout, // [1]
               float* __restrict__ out) {
    extern __shared__ uint32_t smem_u32[];
    uint32_t* Ah = smem_u32 + SM_AH;
    uint32_t* Bh = smem_u32 + SM_BH;
    float* restage = (float*)smem_u32;   // overlays everything after GEMM
    __shared__ float bl_s[64];
    __shared__ float wout_s[64];

    const int tid  = threadIdx.x;
    const int wid  = tid >> 5;
    const int lane = tid & 31;
    const int r0   = blockIdx.x * RBLK;

    if (tid < 64) { bl_s[tid] = bl[tid]; wout_s[tid] = Wout[tid]; }

    // ---- Stage A row (thread = row): x_tx -> kp 0..31, agg -> kp 32..47 ----
    {
        const int r = r0 + tid;
        uint32_t* AR = Ah + tid * A_STR;

        if (r < N_TX) {
            const float4* xr = (const float4*)(x_tx + (size_t)r * 64);
            #pragma unroll
            for (int j = 0; j < 16; j++) {
                float4 v = __ldcs(xr + j);   // streaming: read-once
                AR[j * 2]     = pack_h2(v.x, v.y);
                AR[j * 2 + 1] = pack_h2(v.z, v.w);
            }
        } else {
            #pragma unroll
            for (int j = 0; j < 32; j++) AR[j] = 0u;
        }

        // CSR gather-mean (x_acc default policy -> L2-resident)
        float a[32];
        #pragma unroll
        for (int d = 0; d < 32; d++) a[d] = 0.f;
        int cnt = 0;
        if (r < N_TX) {
            cnt = g_deg[r];
            int end = g_off[r];           // END pointer after place
            int start = end - cnt;
            for (int i = 0; i < cnt; i++) {
                int s = __ldcs(g_sorted_src + start + i);
                const float4* p = (const float4*)(x_acc + (size_t)s * 32);
                #pragma unroll
                for (int j = 0; j < 8; j++) {
                    float4 v = p[j];
                    a[j * 4 + 0] += v.x; a[j * 4 + 1] += v.y;
                    a[j * 4 + 2] += v.z; a[j * 4 + 3] += v.w;
                }
            }
        }
        float inv = 1.f / (float)max(cnt, 1);
        #pragma unroll
        for (int j = 0; j < 16; j++)
            AR[32 + j] = pack_h2(a[j * 2] * inv, a[j * 2 + 1] * inv);
    }

    // ---- Stage B = W^T [96 k][64 n] as f16x2 k-pairs ----
    {
        const int n   = tid & 63;
        const int kp0 = (tid >> 6) * 24;
        for (int kp = kp0; kp < kp0 + 24; kp++) {
            int k0 = kp * 2;
            float w0 = (k0 < 64) ? Wr[k0 * 64 + n] : Wl[(k0 - 64) * 64 + n];
            int k1 = k0 + 1;
            float w1 = (k1 < 64) ? Wr[k1 * 64 + n] : Wl[(k1 - 64) * 64 + n];
            Bh[kp * B_STR + n] = pack_h2(w0, w1);
        }
    }
    __syncthreads();

    const int t  = lane & 3;
    const int g  = lane >> 2;
    const int rb = wid * 32;

    // Accumulators [mtile][ntile][4], seeded with bias
    float acc[2][8][4];
    #pragma unroll
    for (int nt = 0; nt < 8; nt++) {
        float b0 = bl_s[nt * 8 + t * 2];
        float b1 = bl_s[nt * 8 + t * 2 + 1];
        #pragma unroll
        for (int mt = 0; mt < 2; mt++) {
            acc[mt][nt][0] = b0; acc[mt][nt][1] = b1;
            acc[mt][nt][2] = b0; acc[mt][nt][3] = b1;
        }
    }

    #pragma unroll
    for (int kt = 0; kt < 6; kt++) {
        const int kp0 = kt * 8;
        uint32_t af[2][4];
        #pragma unroll
        for (int mt = 0; mt < 2; mt++) {
            const uint32_t* Ap = Ah + (rb + mt * 16 + g) * A_STR + kp0 + t;
            af[mt][0] = Ap[0];                 // (row g,   kp t)
            af[mt][1] = Ap[8 * A_STR];         // (row g+8, kp t)
            af[mt][2] = Ap[4];                 // (row g,   kp t+4)
            af[mt][3] = Ap[8 * A_STR + 4];     // (row g+8, kp t+4)
        }
        #pragma unroll
        for (int nt = 0; nt < 8; nt++) {
            const int n = nt * 8 + g;
            const uint32_t* Bp = Bh + (kp0 + t) * B_STR + n;
            uint32_t bh[2];
            bh[0] = Bp[0];
            bh[1] = Bp[4 * B_STR];
            mma16(acc[0][nt], af[0], bh);
            mma16(acc[1][nt], af[1], bh);
        }
    }
    __syncthreads();   // done reading A/B; reuse smem as restage buffer

    // ---- Epilogue: relu + logit dot + restage ----
    #pragma unroll
    for (int mt = 0; mt < 2; mt++) {
        #pragma unroll
        for (int half = 0; half < 2; half++) {
            const int row = rb + mt * 16 + half * 8 + g;
            float* hrow = restage + row * H_STR;
            float partial = 0.f;
            #pragma unroll
            for (int nt = 0; nt < 8; nt++) {
                float h0 = fmaxf(acc[mt][nt][half * 2 + 0], 0.f);
                float h1 = fmaxf(acc[mt][nt][half * 2 + 1], 0.f);
                int col = nt * 8 + t * 2;
                partial += h0 * wout_s[col] + h1 * wout_s[col + 1];
                *(float2*)(hrow + col) = make_float2(h0, h1);
            }
            partial += __shfl_xor_sync(0xffffffffu, partial, 1);
            partial += __shfl_xor_sync(0xffffffffu, partial, 2);
            int r = r0 + row;
            if (t == 0 && r < N_TX) __stcs(out + r, partial + bout[0]);
        }
    }
    __syncthreads();

    // ---- Coalesced tx_x store (streaming) ----
    {
        const int vr = (N_TX - r0 < RBLK) ? (N_TX - r0) : RBLK;
        float4* dst = (float4*)(out + N_TX + (size_t)r0 * 64);
        #pragma unroll
        for (int i = tid; i < RBLK * 16; i += 128) {
            int row = i >> 4, c = i & 15;
            if (row < vr)
                __stcs(dst + row * 16 + c,
                       *(float4*)(restage + row * H_STR + c * 4));
        }
    }
}

// ---------------------------------------------------------------------------
extern "C" void kernel_launch(void* const* d_in, const int* in_sizes, int n_in,
                              void* d_out, int out_size) {
    const float* x_tx     = (const float*)d_in[0];
    const float* x_acc    = (const float*)d_in[1];
    const int*   pays_src = (const int*)d_in[2];
    const int*   pays_dst = (const int*)d_in[3];
    // d_in[4], d_in[5]: rev edges — dead code in reference (h_acc unused)
    const float* Wl_pays  = (const float*)d_in[6];
    const float* bl_pays  = (const float*)d_in[7];
    const float* Wr_pays  = (const float*)d_in[8];
    // d_in[9..11]: rev weights — unused
    const float* W_out    = (const float*)d_in[12];
    const float* b_out    = (const float*)d_in[13];
    float* out = (float*)d_out;   // [logits(500000) | tx_x(500000*64)]

    cudaFuncSetAttribute(compute_kernel,
                         cudaFuncAttributeMaxDynamicSharedMemorySize, SMEM_BYTES);

    zero_kernel<<<(N_TX + 255) / 256, 256>>>();
    hist_kernel<<<(NE + 255) / 256, 256>>>(pays_dst);
    alloc_kernel<<<N_SCAN_BLKS, SCAN_BS>>>();
    place_kernel<<<(NE + 255) / 256, 256>>>(pays_src, pays_dst);
    compute_kernel<<<(N_TX + RBLK - 1) / RBLK, RBLK, SMEM_BYTES>>>(
        x_tx, x_acc, Wl_pays, bl_pays, Wr_pays, W_out, b_out, out);
}

// round 13
// speedup vs baseline: 3.9818x; 1.3124x over previous
#include <cuda_runtime.h>
#include <cuda_fp16.h>
#include <cstdint>

#define N_TX   500000
#define N_ACC  100000
#define NE     1000000

#define SCAN_BS   1024
#define N_SCAN_BLKS ((N_TX + SCAN_BS - 1) / SCAN_BS)   // 489

#define B_STR  72    // u32; 72%32==8 -> frag bank = 8t+g, bijective

// CSR + prepack scratch
__device__ int g_deg[N_TX];                      // zero-initialized at load;
__device__ int g_off[N_TX];                      // self-zeroed by compute tail
__device__ int g_sorted_src[NE];
__device__ int g_alloc_ctr;
__device__ __align__(16) uint32_t g_xacc_h[N_ACC * 16];  // x_acc as f16x2, 6.4 MB
__device__ __align__(16) uint32_t g_Bpre[48 * B_STR];    // prepacked B (f16x2)

// pack two f32 -> f16x2 (v0 -> low half = even k)
__device__ __forceinline__ uint32_t pack_h2(float v0, float v1) {
    __half2 h = __floats2half2_rn(v0, v1);
    return *(uint32_t*)&h;
}

// ---------------------------------------------------------------------------
// Prepack: x_acc -> fp16 (blocks 0..3124), B = W^T f16x2 (last block)
// ---------------------------------------------------------------------------
__global__ void prepack_kernel(const float* __restrict__ x_acc,
                               const float* __restrict__ Wl,
                               const float* __restrict__ Wr) {
    if (blockIdx.x < 3125) {
        int i = blockIdx.x * 256 + threadIdx.x;   // over N_ACC*8 = 800000 float4
        if (i < N_ACC * 8) {
            float4 v = ((const float4*)x_acc)[i];
            uint2 pk;
            pk.x = pack_h2(v.x, v.y);
            pk.y = pack_h2(v.z, v.w);
            ((uint2*)g_xacc_h)[i] = pk;
        }
    } else {
        int n   = threadIdx.x & 63;
        int kp0 = (threadIdx.x >> 6) * 12;
        for (int kp = kp0; kp < kp0 + 12; kp++) {
            int k0 = kp * 2, k1 = kp * 2 + 1;
            float w0 = (k0 < 64) ? Wr[k0 * 64 + n] : Wl[(k0 - 64) * 64 + n];
            float w1 = (k1 < 64) ? Wr[k1 * 64 + n] : Wl[(k1 - 64) * 64 + n];
            g_Bpre[kp * B_STR + n] = pack_h2(w0, w1);
        }
    }
}

__global__ void hist_kernel(const int* __restrict__ dst_idx) {
    int e = blockIdx.x * blockDim.x + threadIdx.x;
    if (e < NE) atomicAdd(&g_deg[dst_idx[e]], 1);
}

// Fused scan: block-scan + one global atomic per 1024-row block -> absolute g_off
__global__ void alloc_kernel() {
    __shared__ int sh[SCAN_BS];
    __shared__ int base_s;
    int t = threadIdx.x;
    int idx = blockIdx.x * SCAN_BS + t;
    int v = (idx < N_TX) ? g_deg[idx] : 0;
    sh[t] = v;
    __syncthreads();
    #pragma unroll
    for (int o = 1; o < SCAN_BS; o <<= 1) {
        int add = (t >= o) ? sh[t - o] : 0;
        __syncthreads();
        sh[t] += add;
        __syncthreads();
    }
    if (t == SCAN_BS - 1) base_s = atomicAdd(&g_alloc_ctr, sh[t]);
    __syncthreads();
    if (idx < N_TX) g_off[idx] = base_s + sh[t] - v;   // exclusive start
}

__global__ void place_kernel(const int* __restrict__ src_idx,
                             const int* __restrict__ dst_idx) {
    int e = blockIdx.x * blockDim.x + threadIdx.x;
    if (e >= NE) return;
    int pos = atomicAdd(&g_off[dst_idx[e]], 1);
    g_sorted_src[pos] = src_idx[e];
}

// ---------------------------------------------------------------------------
// Fused compute kernel: CSR gather-mean (fp16 source) + [x|agg][128x96] @
// W^T[96x64] via single-product f16 m16n8k16; relu + logit head.
// 128 threads, 4 warps, warp = 32 rows. 40 KB smem -> 5 CTA/SM.
// Tail self-zeros g_deg / g_alloc_ctr for the next graph replay.
// ---------------------------------------------------------------------------
#define RBLK   128
#define A_STR  52    // u32/row; 52%32==20 -> frag bank=(20g+t): bijective
#define H_STR  68    // restage stride (floats)

// dynamic smem (u32 units): Ah | Bh
#define SM_AH  0
#define SM_BH  (RBLK * A_STR)                 // 6656
#define SM_TOT (SM_BH + 48 * B_STR)           // 10112 u32
#define SMEM_BYTES (SM_TOT * 4)               // 40448 B

__device__ __forceinline__ void mma16(float* c, const uint32_t* a, const uint32_t* b) {
    asm volatile(
        "mma.sync.aligned.m16n8k16.row.col.f32.f16.f16.f32 "
        "{%0,%1,%2,%3}, {%4,%5,%6,%7}, {%8,%9}, {%0,%1,%2,%3};"
        : "+f"(c[0]), "+f"(c[1]), "+f"(c[2]), "+f"(c[3])
        : "r"(a[0]), "r"(a[1]), "r"(a[2]), "r"(a[3]), "r"(b[0]), "r"(b[1]));
}

__global__ void __launch_bounds__(128, 5)
compute_kernel(const float* __restrict__ x_tx,
               const float* __restrict__ bl,   // [64]
               const float* __restrict__ Wout, // [64]
               const float* __restrict__ bout, // [1]
               float* __restrict__ out) {
    extern __shared__ uint32_t smem_u32[];
    uint32_t* Ah = smem_u32 + SM_AH;
    uint32_t* Bh = smem_u32 + SM_BH;
    float* restage = (float*)smem_u32;   // overlays everything after GEMM
    __shared__ float bl_s[64];
    __shared__ float wout_s[64];

    const int tid  = threadIdx.x;
    const int wid  = tid >> 5;
    const int lane = tid & 31;
    const int r0   = blockIdx.x * RBLK;

    if (tid < 64) { bl_s[tid] = bl[tid]; wout_s[tid] = Wout[tid]; }

    // ---- Stage A (x_tx part), COALESCED: warp covers 512 contiguous bytes
    //      per LDG.128 (4 lines vs 32 for row-per-thread). ----
    {
        #pragma unroll
        for (int it = 0; it < 16; it++) {
            int idx = tid + it * 128;        // 0..2047
            int row = idx >> 4, j = idx & 15;
            int r = r0 + row;
            float4 v = make_float4(0.f, 0.f, 0.f, 0.f);
            if (r < N_TX) v = __ldcs((const float4*)x_tx + (size_t)r * 16 + j);
            uint2 pk;
            pk.x = pack_h2(v.x, v.y);
            pk.y = pack_h2(v.z, v.w);
            *(uint2*)(Ah + row * A_STR + j * 2) = pk;
        }
    }

    // ---- Stage B: contiguous uint4 copy of prepacked weights ----
    {
        const uint4* src = (const uint4*)g_Bpre;
        uint4* dst = (uint4*)(smem_u32 + SM_BH);
        #pragma unroll
        for (int i = tid; i < (48 * B_STR) / 4; i += 128) dst[i] = src[i];
    }

    // ---- CSR gather-mean from fp16 x_acc (4 LDG.128 per edge-row) ----
    {
        const int r = r0 + tid;
        uint32_t* AR = Ah + tid * A_STR;
        float a[32];
        #pragma unroll
        for (int d = 0; d < 32; d++) a[d] = 0.f;
        int cnt = 0;
        if (r < N_TX) {
            cnt = g_deg[r];
            int end = g_off[r];           // END pointer after place
            int start = end - cnt;
            for (int i = 0; i < cnt; i++) {
                int s = __ldcs(g_sorted_src + start + i);
                const uint4* p = (const uint4*)(g_xacc_h + (size_t)s * 16);
                #pragma unroll
                for (int jj = 0; jj < 4; jj++) {
                    uint4 w = p[jj];
                    float2 f;
                    f = __half22float2(*(__half2*)&w.x);
                    a[jj * 8 + 0] += f.x; a[jj * 8 + 1] += f.y;
                    f = __half22float2(*(__half2*)&w.y);
                    a[jj * 8 + 2] += f.x; a[jj * 8 + 3] += f.y;
                    f = __half22float2(*(__half2*)&w.z);
                    a[jj * 8 + 4] += f.x; a[jj * 8 + 5] += f.y;
                    f = __half22float2(*(__half2*)&w.w);
                    a[jj * 8 + 6] += f.x; a[jj * 8 + 7] += f.y;
                }
            }
        }
        float inv = 1.f / (float)max(cnt, 1);
        #pragma unroll
        for (int j = 0; j < 16; j++)
            AR[32 + j] = pack_h2(a[j * 2] * inv, a[j * 2 + 1] * inv);
    }
    __syncthreads();

    const int t  = lane & 3;
    const int g  = lane >> 2;
    const int rb = wid * 32;

    // Accumulators [mtile][ntile][4], seeded with bias
    float acc[2][8][4];
    #pragma unroll
    for (int nt = 0; nt < 8; nt++) {
        float b0 = bl_s[nt * 8 + t * 2];
        float b1 = bl_s[nt * 8 + t * 2 + 1];
        #pragma unroll
        for (int mt = 0; mt < 2; mt++) {
            acc[mt][nt][0] = b0; acc[mt][nt][1] = b1;
            acc[mt][nt][2] = b0; acc[mt][nt][3] = b1;
        }
    }

    #pragma unroll
    for (int kt = 0; kt < 6; kt++) {
        const int kp0 = kt * 8;
        uint32_t af[2][4];
        #pragma unroll
        for (int mt = 0; mt < 2; mt++) {
            const uint32_t* Ap = Ah + (rb + mt * 16 + g) * A_STR + kp0 + t;
            af[mt][0] = Ap[0];                 // (row g,   kp t)
            af[mt][1] = Ap[8 * A_STR];         // (row g+8, kp t)
            af[mt][2] = Ap[4];                 // (row g,   kp t+4)
            af[mt][3] = Ap[8 * A_STR + 4];     // (row g+8, kp t+4)
        }
        #pragma unroll
        for (int nt = 0; nt < 8; nt++) {
            const int n = nt * 8 + g;
            const uint32_t* Bp = Bh + (kp0 + t) * B_STR + n;
            uint32_t bh[2];
            bh[0] = Bp[0];
            bh[1] = Bp[4 * B_STR];
            mma16(acc[0][nt], af[0], bh);
            mma16(acc[1][nt], af[1], bh);
        }
    }
    __syncthreads();   // done reading A/B; reuse smem as restage buffer

    // ---- Epilogue: relu + logit dot + restage ----
    #pragma unroll
    for (int mt = 0; mt < 2; mt++) {
        #pragma unroll
        for (int half = 0; half < 2; half++) {
            const int row = rb + mt * 16 + half * 8 + g;
            float* hrow = restage + row * H_STR;
            float partial = 0.f;
            #pragma unroll
            for (int nt = 0; nt < 8; nt++) {
                float h0 = fmaxf(acc[mt][nt][half * 2 + 0], 0.f);
                float h1 = fmaxf(acc[mt][nt][half * 2 + 1], 0.f);
                int col = nt * 8 + t * 2;
                partial += h0 * wout_s[col] + h1 * wout_s[col + 1];
                *(float2*)(hrow + col) = make_float2(h0, h1);
            }
            partial += __shfl_xor_sync(0xffffffffu, partial, 1);
            partial += __shfl_xor_sync(0xffffffffu, partial, 2);
            int r = r0 + row;
            if (t == 0 && r < N_TX) __stcs(out + r, partial + bout[0]);
        }
    }
    __syncthreads();

    // ---- Coalesced tx_x store (streaming) ----
    {
        const int vr = (N_TX - r0 < RBLK) ? (N_TX - r0) : RBLK;
        float4* dst = (float4*)(out + N_TX + (size_t)r0 * 64);
        #pragma unroll
        for (int i = tid; i < RBLK * 16; i += 128) {
            int row = i >> 4, c = i & 15;
            if (row < vr)
                __stcs(dst + row * 16 + c,
                       *(float4*)(restage + row * H_STR + c * 4));
        }
    }

    // ---- Self-clean for next replay (stream-ordered; reads of g_deg done) ----
    {
        int r = r0 + tid;
        if (r < N_TX) g_deg[r] = 0;
        if (blockIdx.x == 0 && tid == 0) g_alloc_ctr = 0;
    }
}

// ---------------------------------------------------------------------------
extern "C" void kernel_launch(void* const* d_in, const int* in_sizes, int n_in,
                              void* d_out, int out_size) {
    const float* x_tx     = (const float*)d_in[0];
    const float* x_acc    = (const float*)d_in[1];
    const int*   pays_src = (const int*)d_in[2];
    const int*   pays_dst = (const int*)d_in[3];
    // d_in[4], d_in[5]: rev edges — dead code in reference (h_acc unused)
    const float* Wl_pays  = (const float*)d_in[6];
    const float* bl_pays  = (const float*)d_in[7];
    const float* Wr_pays  = (const float*)d_in[8];
    // d_in[9..11]: rev weights — unused
    const float* W_out    = (const float*)d_in[12];
    const float* b_out    = (const float*)d_in[13];
    float* out = (float*)d_out;   // [logits(500000) | tx_x(500000*64)]

    cudaFuncSetAttribute(compute_kernel,
                         cudaFuncAttributeMaxDynamicSharedMemorySize, SMEM_BYTES);

    prepack_kernel<<<3126, 256>>>(x_acc, Wl_pays, Wr_pays);
    hist_kernel<<<(NE + 255) / 256, 256>>>(pays_dst);
    alloc_kernel<<<N_SCAN_BLKS, SCAN_BS>>>();
    place_kernel<<<(NE + 255) / 256, 256>>>(pays_src, pays_dst);
    compute_kernel<<<(N_TX + RBLK - 1) / RBLK, RBLK, SMEM_BYTES>>>(
        x_tx, bl_pays, W_out, b_out, out);
}

// round 14
// speedup vs baseline: 4.1849x; 1.0510x over previous
#include <cuda_runtime.h>
#include <cuda_fp16.h>
#include <cstdint>

#define N_TX   500000
#define N_ACC  100000
#define NE     1000000

#define SCAN_BS   1024
#define N_SCAN_BLKS ((N_TX + SCAN_BS - 1) / SCAN_BS)   // 489

#define B_STR  72    // u32; 72%32==8 -> frag bank = 8t+g, bijective

// Prepack+hist fused kernel block roles
#define PP_XACC_BLKS 3125                       // N_ACC*8 float4 / 256
#define PP_B_BLK     PP_XACC_BLKS               // 3125
#define PP_HIST0     (PP_B_BLK + 1)             // 3126
#define PP_HIST_BLKS ((NE + 255) / 256)         // 3907
#define PP_GRID      (PP_HIST0 + PP_HIST_BLKS)  // 7033

// CSR + prepack scratch
__device__ int g_deg[N_TX];                      // zero-init at load;
__device__ int g_off[N_TX];                      // self-zeroed by compute tail
__device__ int g_sorted_src[NE];
__device__ int g_alloc_ctr;
__device__ __align__(16) uint32_t g_xacc_h[N_ACC * 16];  // x_acc as f16x2, 6.4 MB
__device__ __align__(16) uint32_t g_Bpre[48 * B_STR];    // prepacked B (f16x2)

// pack two f32 -> f16x2 (v0 -> low half = even k)
__device__ __forceinline__ uint32_t pack_h2(float v0, float v1) {
    __half2 h = __floats2half2_rn(v0, v1);
    return *(uint32_t*)&h;
}

// ---------------------------------------------------------------------------
// K1 (fused): x_acc -> fp16 | B = W^T f16x2 | degree histogram.
// Hist runs concurrently with the bandwidth-bound prepack sections.
// ---------------------------------------------------------------------------
__global__ void prepack_hist_kernel(const float* __restrict__ x_acc,
                                    const float* __restrict__ Wl,
                                    const float* __restrict__ Wr,
                                    const int*   __restrict__ dst_idx) {
    const int bid = blockIdx.x;
    if (bid < PP_XACC_BLKS) {
        int i = bid * 256 + threadIdx.x;          // over N_ACC*8 = 800000 float4
        if (i < N_ACC * 8) {
            float4 v = ((const float4*)x_acc)[i];
            uint2 pk;
            pk.x = pack_h2(v.x, v.y);
            pk.y = pack_h2(v.z, v.w);
            ((uint2*)g_xacc_h)[i] = pk;
        }
    } else if (bid == PP_B_BLK) {
        int n   = threadIdx.x & 63;
        int kp0 = (threadIdx.x >> 6) * 12;
        for (int kp = kp0; kp < kp0 + 12; kp++) {
            int k0 = kp * 2, k1 = kp * 2 + 1;
            float w0 = (k0 < 64) ? Wr[k0 * 64 + n] : Wl[(k0 - 64) * 64 + n];
            float w1 = (k1 < 64) ? Wr[k1 * 64 + n] : Wl[(k1 - 64) * 64 + n];
            g_Bpre[kp * B_STR + n] = pack_h2(w0, w1);
        }
    } else {
        int e = (bid - PP_HIST0) * 256 + threadIdx.x;
        if (e < NE) atomicAdd(&g_deg[dst_idx[e]], 1);
    }
}

// Fused scan: block-scan + one global atomic per 1024-row block -> absolute g_off
__global__ void alloc_kernel() {
    __shared__ int sh[SCAN_BS];
    __shared__ int base_s;
    int t = threadIdx.x;
    int idx = blockIdx.x * SCAN_BS + t;
    int v = (idx < N_TX) ? g_deg[idx] : 0;
    sh[t] = v;
    __syncthreads();
    #pragma unroll
    for (int o = 1; o < SCAN_BS; o <<= 1) {
        int add = (t >= o) ? sh[t - o] : 0;
        __syncthreads();
        sh[t] += add;
        __syncthreads();
    }
    if (t == SCAN_BS - 1) base_s = atomicAdd(&g_alloc_ctr, sh[t]);
    __syncthreads();
    if (idx < N_TX) g_off[idx] = base_s + sh[t] - v;   // exclusive start
}

__global__ void place_kernel(const int* __restrict__ src_idx,
                             const int* __restrict__ dst_idx) {
    int e = blockIdx.x * blockDim.x + threadIdx.x;
    if (e >= NE) return;
    int pos = atomicAdd(&g_off[dst_idx[e]], 1);
    g_sorted_src[pos] = src_idx[e];
}

// ---------------------------------------------------------------------------
// Fused compute kernel: CSR gather-mean (fp16 source, pipelined idx prefetch)
// + [x|agg][128x96] @ W^T[96x64] single-product f16 m16n8k16; relu + logit.
// 128 threads, 4 warps, warp = 32 rows. 40 KB smem -> 5 CTA/SM.
// Tail self-zeros g_deg / g_alloc_ctr for the next graph replay.
// ---------------------------------------------------------------------------
#define RBLK   128
#define A_STR  52    // u32/row; 52%32==20 -> frag bank=(20g+t): bijective
#define H_STR  68    // restage stride (floats)

// dynamic smem (u32 units): Ah | Bh
#define SM_AH  0
#define SM_BH  (RBLK * A_STR)                 // 6656
#define SM_TOT (SM_BH + 48 * B_STR)           // 10112 u32
#define SMEM_BYTES (SM_TOT * 4)               // 40448 B

__device__ __forceinline__ void mma16(float* c, const uint32_t* a, const uint32_t* b) {
    asm volatile(
        "mma.sync.aligned.m16n8k16.row.col.f32.f16.f16.f32 "
        "{%0,%1,%2,%3}, {%4,%5,%6,%7}, {%8,%9}, {%0,%1,%2,%3};"
        : "+f"(c[0]), "+f"(c[1]), "+f"(c[2]), "+f"(c[3])
        : "r"(a[0]), "r"(a[1]), "r"(a[2]), "r"(a[3]), "r"(b[0]), "r"(b[1]));
}

__global__ void __launch_bounds__(128, 5)
compute_kernel(const float* __restrict__ x_tx,
               const float* __restrict__ bl,   // [64]
               const float* __restrict__ Wout, // [64]
               const float* __restrict__ bout, // [1]
               float* __restrict__ out) {
    extern __shared__ uint32_t smem_u32[];
    uint32_t* Ah = smem_u32 + SM_AH;
    uint32_t* Bh = smem_u32 + SM_BH;
    float* restage = (float*)smem_u32;   // overlays everything after GEMM
    __shared__ float bl_s[64];
    __shared__ float wout_s[64];

    const int tid  = threadIdx.x;
    const int wid  = tid >> 5;
    const int lane = tid & 31;
    const int r0   = blockIdx.x * RBLK;

    if (tid < 64) { bl_s[tid] = bl[tid]; wout_s[tid] = Wout[tid]; }

    // ---- Stage A (x_tx part), coalesced: warp covers 512 contiguous bytes ----
    {
        #pragma unroll
        for (int it = 0; it < 16; it++) {
            int idx = tid + it * 128;        // 0..2047
            int row = idx >> 4, j = idx & 15;
            int r = r0 + row;
            float4 v = make_float4(0.f, 0.f, 0.f, 0.f);
            if (r < N_TX) v = __ldcs((const float4*)x_tx + (size_t)r * 16 + j);
            uint2 pk;
            pk.x = pack_h2(v.x, v.y);
            pk.y = pack_h2(v.z, v.w);
            *(uint2*)(Ah + row * A_STR + j * 2) = pk;
        }
    }

    // ---- Stage B: contiguous uint4 copy of prepacked weights ----
    {
        const uint4* src = (const uint4*)g_Bpre;
        uint4* dst = (uint4*)(smem_u32 + SM_BH);
        #pragma unroll
        for (int i = tid; i < (48 * B_STR) / 4; i += 128) dst[i] = src[i];
    }

    // ---- CSR gather-mean from fp16 x_acc, idx-prefetch pipelined ----
    {
        const int r = r0 + tid;
        uint32_t* AR = Ah + tid * A_STR;
        float a[32];
        #pragma unroll
        for (int d = 0; d < 32; d++) a[d] = 0.f;
        int cnt = 0;
        if (r < N_TX) {
            cnt = g_deg[r];
            int end = g_off[r];           // END pointer after place
            int start = end - cnt;
            if (cnt > 0) {
                int s = __ldcs(g_sorted_src + start);
                for (int i = 0; i < cnt; i++) {
                    int s_next = (i + 1 < cnt) ? __ldcs(g_sorted_src + start + i + 1) : 0;
                    const uint4* p = (const uint4*)(g_xacc_h + (size_t)s * 16);
                    #pragma unroll
                    for (int jj = 0; jj < 4; jj++) {
                        uint4 w = p[jj];
                        float2 f;
                        f = __half22float2(*(__half2*)&w.x);
                        a[jj * 8 + 0] += f.x; a[jj * 8 + 1] += f.y;
                        f = __half22float2(*(__half2*)&w.y);
                        a[jj * 8 + 2] += f.x; a[jj * 8 + 3] += f.y;
                        f = __half22float2(*(__half2*)&w.z);
                        a[jj * 8 + 4] += f.x; a[jj * 8 + 5] += f.y;
                        f = __half22float2(*(__half2*)&w.w);
                        a[jj * 8 + 6] += f.x; a[jj * 8 + 7] += f.y;
                    }
                    s = s_next;
                }
            }
        }
        float inv = 1.f / (float)max(cnt, 1);
        #pragma unroll
        for (int j = 0; j < 16; j++)
            AR[32 + j] = pack_h2(a[j * 2] * inv, a[j * 2 + 1] * inv);
    }
    __syncthreads();

    const int t  = lane & 3;
    const int g  = lane >> 2;
    const int rb = wid * 32;

    // Accumulators [mtile][ntile][4], seeded with bias
    float acc[2][8][4];
    #pragma unroll
    for (int nt = 0; nt < 8; nt++) {
        float b0 = bl_s[nt * 8 + t * 2];
        float b1 = bl_s[nt * 8 + t * 2 + 1];
        #pragma unroll
        for (int mt = 0; mt < 2; mt++) {
            acc[mt][nt][0] = b0; acc[mt][nt][1] = b1;
            acc[mt][nt][2] = b0; acc[mt][nt][3] = b1;
        }
    }

    #pragma unroll
    for (int kt = 0; kt < 6; kt++) {
        const int kp0 = kt * 8;
        uint32_t af[2][4];
        #pragma unroll
        for (int mt = 0; mt < 2; mt++) {
            const uint32_t* Ap = Ah + (rb + mt * 16 + g) * A_STR + kp0 + t;
            af[mt][0] = Ap[0];                 // (row g,   kp t)
            af[mt][1] = Ap[8 * A_STR];         // (row g+8, kp t)
            af[mt][2] = Ap[4];                 // (row g,   kp t+4)
            af[mt][3] = Ap[8 * A_STR + 4];     // (row g+8, kp t+4)
        }
        #pragma unroll
        for (int nt = 0; nt < 8; nt++) {
            const int n = nt * 8 + g;
            const uint32_t* Bp = Bh + (kp0 + t) * B_STR + n;
            uint32_t bh[2];
            bh[0] = Bp[0];
            bh[1] = Bp[4 * B_STR];
            mma16(acc[0][nt], af[0], bh);
            mma16(acc[1][nt], af[1], bh);
        }
    }
    __syncthreads();   // done reading A/B; reuse smem as restage buffer

    // ---- Epilogue: relu + logit dot + restage ----
    #pragma unroll
    for (int mt = 0; mt < 2; mt++) {
        #pragma unroll
        for (int half = 0; half < 2; half++) {
            const int row = rb + mt * 16 + half * 8 + g;
            float* hrow = restage + row * H_STR;
            float partial = 0.f;
            #pragma unroll
            for (int nt = 0; nt < 8; nt++) {
                float h0 = fmaxf(acc[mt][nt][half * 2 + 0], 0.f);
                float h1 = fmaxf(acc[mt][nt][half * 2 + 1], 0.f);
                int col = nt * 8 + t * 2;
                partial += h0 * wout_s[col] + h1 * wout_s[col + 1];
                *(float2*)(hrow + col) = make_float2(h0, h1);
            }
            partial += __shfl_xor_sync(0xffffffffu, partial, 1);
            partial += __shfl_xor_sync(0xffffffffu, partial, 2);
            int r = r0 + row;
            if (t == 0 && r < N_TX) __stcs(out + r, partial + bout[0]);
        }
    }
    __syncthreads();

    // ---- Coalesced tx_x store (streaming) ----
    {
        const int vr = (N_TX - r0 < RBLK) ? (N_TX - r0) : RBLK;
        float4* dst = (float4*)(out + N_TX + (size_t)r0 * 64);
        #pragma unroll
        for (int i = tid; i < RBLK * 16; i += 128) {
            int row = i >> 4, c = i & 15;
            if (row < vr)
                __stcs(dst + row * 16 + c,
                       *(float4*)(restage + row * H_STR + c * 4));
        }
    }

    // ---- Self-clean for next replay (stream-ordered; g_deg reads done) ----
    {
        int r = r0 + tid;
        if (r < N_TX) g_deg[r] = 0;
        if (blockIdx.x == 0 && tid == 0) g_alloc_ctr = 0;
    }
}

// ---------------------------------------------------------------------------
extern "C" void kernel_launch(void* const* d_in, const int* in_sizes, int n_in,
                              void* d_out, int out_size) {
    const float* x_tx     = (const float*)d_in[0];
    const float* x_acc    = (const float*)d_in[1];
    const int*   pays_src = (const int*)d_in[2];
    const int*   pays_dst = (const int*)d_in[3];
    // d_in[4], d_in[5]: rev edges — dead code in reference (h_acc unused)
    const float* Wl_pays  = (const float*)d_in[6];
    const float* bl_pays  = (const float*)d_in[7];
    const float* Wr_pays  = (const float*)d_in[8];
    // d_in[9..11]: rev weights — unused
    const float* W_out    = (const float*)d_in[12];
    const float* b_out    = (const float*)d_in[13];
    float* out = (float*)d_out;   // [logits(500000) | tx_x(500000*64)]

    cudaFuncSetAttribute(compute_kernel,
                         cudaFuncAttributeMaxDynamicSharedMemorySize, SMEM_BYTES);

    prepack_hist_kernel<<<PP_GRID, 256>>>(x_acc, Wl_pays, Wr_pays, pays_dst);
    alloc_kernel<<<N_SCAN_BLKS, SCAN_BS>>>();
    place_kernel<<<(NE + 255) / 256, 256>>>(pays_src, pays_dst);
    compute_kernel<<<(N_TX + RBLK - 1) / RBLK, RBLK, SMEM_BYTES>>>(
        x_tx, bl_pays, W_out, b_out, out);
}